// round 16
// baseline (speedup 1.0000x reference)
#include <cuda_runtime.h>
#include <cuda_fp16.h>
#include <cstdint>

#define NMAX 50000
#define EMAX 500000
#define DIN  128   // input feature dim
#define H1   256   // conv1 output dim
#define H2   128   // conv2 output dim
#define DOUT 6
#define CAP  64    // ELL bucket capacity

// ---------------- scratch (device globals; no allocation allowed) ----------
__device__ __half g_xh  [NMAX * DIN];   // d_s * x_s, fp16 (pre-scaled)
__device__ __half g_accX[NMAX * DIN];   // layer-1 aggregate, fp16 (GEMM1 A)
__device__ __half g_h1  [NMAX * H1];    // relu(conv1), fp16 (GEMM2 A)
__device__ __half g_g2h [NMAX * H2];    // d_i*(h1@W2), fp16
__device__ __half g_W1h [H1 * DIN];     // W1 transposed [n][k], fp16
__device__ __half g_W2h [H2 * H1];      // W2 transposed [n][k], fp16
__device__ int    g_cnt [NMAX];         // in-degree counter (self-clearing)
__device__ int    g_eidx[NMAX * CAP];   // ELL neighbor (src) indices

__device__ __forceinline__ float disq(int cnt) {  // (deg+1)^{-1/2}
    return rsqrtf((float)(cnt + 1));
}

// ---------------- packed f32x2 add (exact, element-wise) --------------------
__device__ __forceinline__ void fadd2(float2& a, float2 b) {
    asm("add.rn.f32x2 %0, %0, %1;"
        : "+l"(*reinterpret_cast<unsigned long long*>(&a))
        : "l"(*reinterpret_cast<const unsigned long long*>(&b)));
}

// ---------------- ELL fill + weight convert (merged, disjoint blocks) -------
__global__ void k_fillround(const int* __restrict__ src, const int* __restrict__ dst,
                            int E, int fillBlocks,
                            const float* __restrict__ W1, const float* __restrict__ W2) {
    if ((int)blockIdx.x < fillBlocks) {
        int i = blockIdx.x * blockDim.x + threadIdx.x;
        if (i < E) {
            int d = dst[i];
            int pos = atomicAdd(&g_cnt[d], 1);
            if (pos < CAP) g_eidx[d * CAP + pos] = src[i];
        }
    } else {
        int i = (blockIdx.x - fillBlocks) * blockDim.x + threadIdx.x;
        if (i < DIN * H1) {
            int k = i / H1, nn = i % H1;
            g_W1h[nn * DIN + k] = __float2half_rn(W1[i]);
        }
        if (i < H1 * H2) {
            int k = i / H2, nn = i % H2;
            g_W2h[nn * H1 + k] = __float2half_rn(W2[i]);
        }
    }
}

// ---------------- prep: x -> fp16, pre-scaled by d_s ------------------------
__global__ void k_xhalf(const float* __restrict__ x, int n) {
    int i = blockIdx.x * blockDim.x + threadIdx.x;   // float4 index
    if (i >= n * 32) return;
    int row = i >> 5;
    float s = disq(g_cnt[row]);
    float4 v = ((const float4*)x)[i];
    __half2 h0 = __floats2half2_rn(v.x * s, v.y * s);
    __half2 h1 = __floats2half2_rn(v.z * s, v.w * s);
    uint2 o;
    o.x = *reinterpret_cast<const unsigned*>(&h0);
    o.y = *reinterpret_cast<const unsigned*>(&h1);
    ((uint2*)g_xh)[i] = o;
}

// ---------------- half gather chunk: C independent neighbor sums ------------
template <int C>
__device__ __forceinline__ void gather_chunk_h(const __half* __restrict__ feat,
                                               int j, int lane,
                                               float2& acc01, float2& acc23) {
    int id[C];
#pragma unroll
    for (int u = 0; u < C; u++) id[u] = g_eidx[j + u];
    uint2 v[C];
#pragma unroll
    for (int u = 0; u < C; u++)
        v[u] = ((const uint2*)feat)[(size_t)id[u] * 32 + lane];
#pragma unroll
    for (int u = 0; u < C; u++) {
        fadd2(acc01, __half22float2(*reinterpret_cast<__half2*>(&v[u].x)));
        fadd2(acc23, __half22float2(*reinterpret_cast<__half2*>(&v[u].y)));
    }
}

__device__ __forceinline__ void gather_row_h(const __half* __restrict__ feat,
                                             int beg, int len, int lane,
                                             float2& acc01, float2& acc23) {
    int j = beg, rem = len;
    while (rem >= 8) { gather_chunk_h<8>(feat, j, lane, acc01, acc23); j += 8; rem -= 8; }
    if (rem >= 4)    { gather_chunk_h<4>(feat, j, lane, acc01, acc23); j += 4; rem -= 4; }
    if (rem >= 2)    { gather_chunk_h<2>(feat, j, lane, acc01, acc23); j += 2; rem -= 2; }
    if (rem)         { gather_chunk_h<1>(feat, j, lane, acc01, acc23); }
}

// ---------------- layer-1 gather: g_accX[v] = d_v * sum(pre-scaled rows) ----
__global__ void k_gather1(int n) {
    int gtid = blockIdx.x * blockDim.x + threadIdx.x;
    int w = gtid >> 5;
    int lane = threadIdx.x & 31;
    if (w >= n) return;

    int cnt = g_cnt[w];
    int len = min(cnt, CAP);
    float s = disq(cnt);

    uint2 xv = ((const uint2*)g_xh)[(size_t)w * 32 + lane];
    float2 acc01 = __half22float2(*reinterpret_cast<__half2*>(&xv.x));
    float2 acc23 = __half22float2(*reinterpret_cast<__half2*>(&xv.y));

    gather_row_h(g_xh, w * CAP, len, lane, acc01, acc23);

    __half2 o0 = __floats2half2_rn(acc01.x * s, acc01.y * s);
    __half2 o1 = __floats2half2_rn(acc23.x * s, acc23.y * s);
    uint2 o;
    o.x = *reinterpret_cast<const unsigned*>(&o0);
    o.y = *reinterpret_cast<const unsigned*>(&o1);
    ((uint2*)g_accX)[(size_t)w * 32 + lane] = o;
}

// ---------------- cp.async / ldmatrix / mma helpers -------------------------
__device__ __forceinline__ void cpa16(void* dst, const void* src, int srcbytes) {
    uint32_t d = (uint32_t)__cvta_generic_to_shared(dst);
    asm volatile("cp.async.cg.shared.global [%0], [%1], 16, %2;"
                 :: "r"(d), "l"(src), "r"(srcbytes));
}
__device__ __forceinline__ void cpa_commit() {
    asm volatile("cp.async.commit_group;");
}
template <int N>
__device__ __forceinline__ void cpa_wait() {
    asm volatile("cp.async.wait_group %0;" :: "n"(N));
}

__device__ __forceinline__ void ldsm4(uint32_t& r0, uint32_t& r1, uint32_t& r2,
                                      uint32_t& r3, uint32_t addr) {
    asm volatile("ldmatrix.sync.aligned.m8n8.x4.shared.b16 {%0,%1,%2,%3}, [%4];"
                 : "=r"(r0), "=r"(r1), "=r"(r2), "=r"(r3) : "r"(addr));
}

__device__ __forceinline__ void mma_f16(float& c0, float& c1, float& c2, float& c3,
                                        uint32_t a0, uint32_t a1, uint32_t a2, uint32_t a3,
                                        uint32_t b0, uint32_t b1) {
    asm volatile(
        "mma.sync.aligned.m16n8k16.row.col.f32.f16.f16.f32 "
        "{%0,%1,%2,%3},{%4,%5,%6,%7},{%8,%9},{%0,%1,%2,%3};"
        : "+f"(c0), "+f"(c1), "+f"(c2), "+f"(c3)
        : "r"(a0), "r"(a1), "r"(a2), "r"(a3), "r"(b0), "r"(b1));
}

// ---------------- fp16 tensor-core GEMM: whole-K panels, barrier-free loop --
// CTA 128x128, 256 thr = 8 warps (2 x 4), warp tile 64x32.
// A [m][k], B [n][k] fp16 panels fully resident in dynamic smem (stride K+8):
// one cp.async group + ONE barrier, then K/16 fully-unrolled ldsm+mma steps
// with no synchronization at all.
// MODE 1 (conv1): K=128, A=g_accX, B=g_W1h; C = half(relu(v+b1)) -> g_h1
// MODE 2 (conv2): K=256, A=g_h1,   B=g_W2h; C = half(d_row * v)  -> g_g2h
extern __shared__ __half dsm_h[];

template <int MODE>
__global__ __launch_bounds__(256, (MODE == 1) ? 2 : 1)
void k_gemm_h(const float* __restrict__ bias, int M, int N) {
    const int K   = (MODE == 1) ? DIN : H1;
    const int STR = K + 8;                 // halves per smem row (ldsm conflict-free)

    __half* As = dsm_h;
    __half* Bs = dsm_h + 128 * STR;

    const __half* A  = (MODE == 1) ? g_accX : g_h1;
    const __half* Bw = (MODE == 1) ? g_W1h  : g_W2h;

    int tid  = threadIdx.x;
    int lane = tid & 31;
    int wid  = tid >> 5;
    int warp_m = wid & 1;   // 0..1 (64 rows)
    int warp_n = wid >> 1;  // 0..3 (32 cols)
    int bm = blockIdx.x * 128;
    int bn = blockIdx.y * 128;
    int lq = lane & 3;
    int lg = lane >> 2;

    float c[4][4][4];
#pragma unroll
    for (int mt = 0; mt < 4; mt++)
#pragma unroll
        for (int nt = 0; nt < 4; nt++)
#pragma unroll
            for (int r = 0; r < 4; r++) c[mt][nt][r] = 0.f;

    // ---- load whole A and B panels (one async group, one barrier) ----
    const int CPR = K / 8;                 // 16B chunks per row
    const int QN  = 128 * CPR / 256;       // chunks per thread per panel
#pragma unroll
    for (int q = 0; q < QN; q++) {
        int idx = q * 256 + tid;
        int r   = idx / CPR;
        int ck  = idx % CPR;
        int gr  = bm + r;
        int ok  = (gr < M) ? 16 : 0;
        cpa16(&As[r * STR + ck * 8], A + (size_t)min(gr, M - 1) * K + ck * 8, ok);
        cpa16(&Bs[r * STR + ck * 8], Bw + (size_t)(bn + r) * K + ck * 8, 16);
    }
    cpa_commit();
    cpa_wait<0>();
    __syncthreads();

    // ---- barrier-free main loop over K ----
    uint32_t asb = (uint32_t)__cvta_generic_to_shared(As);
    uint32_t bsb = (uint32_t)__cvta_generic_to_shared(Bs);
    uint32_t lmOff = ((lane & 15) * STR + (lane >> 4) * 8) * 2;

#pragma unroll
    for (int ks = 0; ks < K / 16; ks++) {
        uint32_t kOff = ks * 16 * 2;
        uint32_t a[4][4];
#pragma unroll
        for (int mt = 0; mt < 4; mt++) {
            uint32_t addr = asb + (warp_m * 64 + mt * 16) * (STR * 2) + kOff + lmOff;
            ldsm4(a[mt][0], a[mt][1], a[mt][2], a[mt][3], addr);
        }
        uint32_t b[4][2];
#pragma unroll
        for (int ntp = 0; ntp < 2; ntp++) {
            uint32_t r0, r1, r2, r3;
            uint32_t addr = bsb + (warp_n * 32 + ntp * 16) * (STR * 2) + kOff + lmOff;
            ldsm4(r0, r1, r2, r3, addr);
            b[ntp * 2 + 0][0] = r0;
            b[ntp * 2 + 1][0] = r1;
            b[ntp * 2 + 0][1] = r2;
            b[ntp * 2 + 1][1] = r3;
        }
#pragma unroll
        for (int mt = 0; mt < 4; mt++)
#pragma unroll
            for (int nt = 0; nt < 4; nt++)
                mma_f16(c[mt][nt][0], c[mt][nt][1], c[mt][nt][2], c[mt][nt][3],
                        a[mt][0], a[mt][1], a[mt][2], a[mt][3],
                        b[nt][0], b[nt][1]);
    }

    // ---- epilogue ----
#pragma unroll
    for (int mt = 0; mt < 4; mt++) {
        int row0 = bm + warp_m * 64 + mt * 16 + lg;
        int row1 = row0 + 8;
#pragma unroll
        for (int nt = 0; nt < 4; nt++) {
            int col = bn + warp_n * 32 + nt * 8 + lq * 2;
            if (MODE == 1) {
                float2 bb = *(const float2*)(bias + col);
                if (row0 < M) {
                    __half2 v = __floats2half2_rn(fmaxf(c[mt][nt][0] + bb.x, 0.f),
                                                  fmaxf(c[mt][nt][1] + bb.y, 0.f));
                    *(unsigned*)(g_h1 + (size_t)row0 * N + col) =
                        *reinterpret_cast<const unsigned*>(&v);
                }
                if (row1 < M) {
                    __half2 v = __floats2half2_rn(fmaxf(c[mt][nt][2] + bb.x, 0.f),
                                                  fmaxf(c[mt][nt][3] + bb.y, 0.f));
                    *(unsigned*)(g_h1 + (size_t)row1 * N + col) =
                        *reinterpret_cast<const unsigned*>(&v);
                }
            } else {
                if (row0 < M) {
                    float s0 = disq(g_cnt[row0]);
                    __half2 v = __floats2half2_rn(c[mt][nt][0] * s0, c[mt][nt][1] * s0);
                    *(unsigned*)(g_g2h + (size_t)row0 * N + col) =
                        *reinterpret_cast<const unsigned*>(&v);
                }
                if (row1 < M) {
                    float s1 = disq(g_cnt[row1]);
                    __half2 v = __floats2half2_rn(c[mt][nt][2] * s1, c[mt][nt][3] * s1);
                    *(unsigned*)(g_g2h + (size_t)row1 * N + col) =
                        *reinterpret_cast<const unsigned*>(&v);
                }
            }
        }
    }
}

// ---------------- fused layer-2 gather + FC head (clears g_cnt) -------------
__global__ void k_gather2fc(const float* __restrict__ Wfc, const float* __restrict__ bfc,
                            const float* __restrict__ b2, float* __restrict__ out, int n) {
    int gtid = blockIdx.x * blockDim.x + threadIdx.x;
    int w = gtid >> 5;
    int lane = threadIdx.x & 31;
    if (w >= n) return;

    int cnt = g_cnt[w];
    int len = min(cnt, CAP);
    float s = disq(cnt);

    uint2 gv = ((const uint2*)g_g2h)[(size_t)w * 32 + lane];
    float2 acc01 = __half22float2(*reinterpret_cast<__half2*>(&gv.x));
    float2 acc23 = __half22float2(*reinterpret_cast<__half2*>(&gv.y));

    gather_row_h(g_g2h, w * CAP, len, lane, acc01, acc23);

    if (lane == 0) g_cnt[w] = 0;   // self-clear for next replay

    float4 bb = ((const float4*)b2)[lane];
    float h[4];
    h[0] = fmaxf(acc01.x * s + bb.x, 0.f);
    h[1] = fmaxf(acc01.y * s + bb.y, 0.f);
    h[2] = fmaxf(acc23.x * s + bb.z, 0.f);
    h[3] = fmaxf(acc23.y * s + bb.w, 0.f);

    int c0 = lane * 4;
    float a6[DOUT];
#pragma unroll
    for (int o = 0; o < DOUT; o++) a6[o] = 0.f;
#pragma unroll
    for (int j = 0; j < 4; j++)
#pragma unroll
        for (int o = 0; o < DOUT; o++)
            a6[o] += h[j] * __ldg(&Wfc[(c0 + j) * DOUT + o]);
#pragma unroll
    for (int o = 0; o < DOUT; o++)
        for (int off = 16; off; off >>= 1)
            a6[o] += __shfl_xor_sync(0xffffffffu, a6[o], off);
    if (lane == 0) {
#pragma unroll
        for (int o = 0; o < DOUT; o++) out[(size_t)w * DOUT + o] = a6[o] + bfc[o];
    }
}

// ---------------- launch ----------------------------------------------------
extern "C" void kernel_launch(void* const* d_in, const int* in_sizes, int n_in,
                              void* d_out, int out_size) {
    const float* x   = (const float*)d_in[0];
    const float* W1  = (const float*)d_in[1];
    const float* b1  = (const float*)d_in[2];
    const float* W2  = (const float*)d_in[3];
    const float* b2  = (const float*)d_in[4];
    const float* Wfc = (const float*)d_in[5];
    const float* bfc = (const float*)d_in[6];
    const int*   ei  = (const int*)d_in[7];

    int n = in_sizes[0] / DIN;
    int E = in_sizes[7] / 2;
    const int* src = ei;
    const int* dst = ei + E;
    float* out = (float*)d_out;

    // dynamic smem opt-in (host-side attribute set; not a stream op)
    const int SM1 = 2 * 128 * (DIN + 8) * 2;   // 69,632 B  (2 CTAs/SM)
    const int SM2 = 2 * 128 * (H1  + 8) * 2;   // 135,168 B (1 CTA/SM)
    static bool attr_done = false;
    if (!attr_done) {
        cudaFuncSetAttribute(k_gemm_h<1>, cudaFuncAttributeMaxDynamicSharedMemorySize, SM1);
        cudaFuncSetAttribute(k_gemm_h<2>, cudaFuncAttributeMaxDynamicSharedMemorySize, SM2);
        attr_done = true;
    }

    // adjacency + degrees + weight convert (merged)
    int fillBlocks = (E + 255) / 256;
    int roundBlocks = (DIN * H1 + 255) / 256;
    k_fillround<<<fillBlocks + roundBlocks, 256>>>(src, dst, E, fillBlocks, W1, W2);
    k_xhalf<<<(n * 32 + 255) / 256, 256>>>(x, n);

    // layer 1
    k_gather1<<<(n * 32 + 255) / 256, 256>>>(n);
    {
        dim3 grid((n + 127) / 128, H1 / 128);
        k_gemm_h<1><<<grid, 256, SM1>>>(b1, n, H1);
    }

    // layer 2
    {
        dim3 grid((n + 127) / 128, H2 / 128);
        k_gemm_h<2><<<grid, 256, SM2>>>(nullptr, n, H2);
    }
    k_gather2fc<<<(n * 32 + 255) / 256, 256>>>(Wfc, bfc, b2, out, n);
}

// round 17
// speedup vs baseline: 1.0325x; 1.0325x over previous
#include <cuda_runtime.h>
#include <cuda_fp16.h>
#include <cstdint>

#define NMAX 50000
#define EMAX 500000
#define DIN  128   // input feature dim
#define H1   256   // conv1 output dim
#define H2   128   // conv2 output dim
#define DOUT 6
#define CAP  64    // ELL bucket capacity

#define KC   128               // K-chunk per smem load
#define STR  (KC + 8)          // smem row stride in halves (ldsm conflict-free)

// ---------------- scratch (device globals; no allocation allowed) ----------
__device__ __half g_xh  [NMAX * DIN];   // d_s * x_s, fp16 (pre-scaled)
__device__ __half g_accX[NMAX * DIN];   // layer-1 aggregate, fp16 (GEMM1 A)
__device__ __half g_h1  [NMAX * H1];    // relu(conv1), fp16 (GEMM2 A)
__device__ __half g_g2h [NMAX * H2];    // d_i*(h1@W2), fp16
__device__ __half g_W1h [H1 * DIN];     // W1 transposed [n][k], fp16
__device__ __half g_W2h [H2 * H1];      // W2 transposed [n][k], fp16
__device__ int    g_cnt [NMAX];         // in-degree counter (self-clearing)
__device__ int    g_eidx[NMAX * CAP];   // ELL neighbor (src) indices

__device__ __forceinline__ float disq(int cnt) {  // (deg+1)^{-1/2}
    return rsqrtf((float)(cnt + 1));
}

// ---------------- packed f32x2 add (exact, element-wise) --------------------
__device__ __forceinline__ void fadd2(float2& a, float2 b) {
    asm("add.rn.f32x2 %0, %0, %1;"
        : "+l"(*reinterpret_cast<unsigned long long*>(&a))
        : "l"(*reinterpret_cast<const unsigned long long*>(&b)));
}

// ---------------- ELL fill + weight convert (merged, disjoint blocks) -------
__global__ void k_fillround(const int* __restrict__ src, const int* __restrict__ dst,
                            int E, int fillBlocks,
                            const float* __restrict__ W1, const float* __restrict__ W2) {
    if ((int)blockIdx.x < fillBlocks) {
        int i = blockIdx.x * blockDim.x + threadIdx.x;
        if (i < E) {
            int d = dst[i];
            int pos = atomicAdd(&g_cnt[d], 1);
            if (pos < CAP) g_eidx[d * CAP + pos] = src[i];
        }
    } else {
        int i = (blockIdx.x - fillBlocks) * blockDim.x + threadIdx.x;
        if (i < DIN * H1) {
            int k = i / H1, nn = i % H1;
            g_W1h[nn * DIN + k] = __float2half_rn(W1[i]);
        }
        if (i < H1 * H2) {
            int k = i / H2, nn = i % H2;
            g_W2h[nn * H1 + k] = __float2half_rn(W2[i]);
        }
    }
}

// ---------------- prep: x -> fp16, pre-scaled by d_s ------------------------
__global__ void k_xhalf(const float* __restrict__ x, int n) {
    int i = blockIdx.x * blockDim.x + threadIdx.x;   // float4 index
    if (i >= n * 32) return;
    int row = i >> 5;
    float s = disq(g_cnt[row]);
    float4 v = ((const float4*)x)[i];
    __half2 h0 = __floats2half2_rn(v.x * s, v.y * s);
    __half2 h1 = __floats2half2_rn(v.z * s, v.w * s);
    uint2 o;
    o.x = *reinterpret_cast<const unsigned*>(&h0);
    o.y = *reinterpret_cast<const unsigned*>(&h1);
    ((uint2*)g_xh)[i] = o;
}

// ---------------- half gather chunk: C independent neighbor sums ------------
template <int C>
__device__ __forceinline__ void gather_chunk_h(const __half* __restrict__ feat,
                                               int j, int lane,
                                               float2& acc01, float2& acc23) {
    int id[C];
#pragma unroll
    for (int u = 0; u < C; u++) id[u] = g_eidx[j + u];
    uint2 v[C];
#pragma unroll
    for (int u = 0; u < C; u++)
        v[u] = ((const uint2*)feat)[(size_t)id[u] * 32 + lane];
#pragma unroll
    for (int u = 0; u < C; u++) {
        fadd2(acc01, __half22float2(*reinterpret_cast<__half2*>(&v[u].x)));
        fadd2(acc23, __half22float2(*reinterpret_cast<__half2*>(&v[u].y)));
    }
}

__device__ __forceinline__ void gather_row_h(const __half* __restrict__ feat,
                                             int beg, int len, int lane,
                                             float2& acc01, float2& acc23) {
    int j = beg, rem = len;
    while (rem >= 8) { gather_chunk_h<8>(feat, j, lane, acc01, acc23); j += 8; rem -= 8; }
    if (rem >= 4)    { gather_chunk_h<4>(feat, j, lane, acc01, acc23); j += 4; rem -= 4; }
    if (rem >= 2)    { gather_chunk_h<2>(feat, j, lane, acc01, acc23); j += 2; rem -= 2; }
    if (rem)         { gather_chunk_h<1>(feat, j, lane, acc01, acc23); }
}

// ---------------- layer-1 gather: g_accX[v] = d_v * sum(pre-scaled rows) ----
__global__ void k_gather1(int n) {
    int gtid = blockIdx.x * blockDim.x + threadIdx.x;
    int w = gtid >> 5;
    int lane = threadIdx.x & 31;
    if (w >= n) return;

    int cnt = g_cnt[w];
    int len = min(cnt, CAP);
    float s = disq(cnt);

    uint2 xv = ((const uint2*)g_xh)[(size_t)w * 32 + lane];
    float2 acc01 = __half22float2(*reinterpret_cast<__half2*>(&xv.x));
    float2 acc23 = __half22float2(*reinterpret_cast<__half2*>(&xv.y));

    gather_row_h(g_xh, w * CAP, len, lane, acc01, acc23);

    __half2 o0 = __floats2half2_rn(acc01.x * s, acc01.y * s);
    __half2 o1 = __floats2half2_rn(acc23.x * s, acc23.y * s);
    uint2 o;
    o.x = *reinterpret_cast<const unsigned*>(&o0);
    o.y = *reinterpret_cast<const unsigned*>(&o1);
    ((uint2*)g_accX)[(size_t)w * 32 + lane] = o;
}

// ---------------- cp.async / ldmatrix / mma helpers -------------------------
__device__ __forceinline__ void cpa16(void* dst, const void* src, int srcbytes) {
    uint32_t d = (uint32_t)__cvta_generic_to_shared(dst);
    asm volatile("cp.async.cg.shared.global [%0], [%1], 16, %2;"
                 :: "r"(d), "l"(src), "r"(srcbytes));
}
__device__ __forceinline__ void cpa_commit() {
    asm volatile("cp.async.commit_group;");
}
template <int N>
__device__ __forceinline__ void cpa_wait() {
    asm volatile("cp.async.wait_group %0;" :: "n"(N));
}

__device__ __forceinline__ void ldsm4(uint32_t& r0, uint32_t& r1, uint32_t& r2,
                                      uint32_t& r3, uint32_t addr) {
    asm volatile("ldmatrix.sync.aligned.m8n8.x4.shared.b16 {%0,%1,%2,%3}, [%4];"
                 : "=r"(r0), "=r"(r1), "=r"(r2), "=r"(r3) : "r"(addr));
}

__device__ __forceinline__ void mma_f16(float& c0, float& c1, float& c2, float& c3,
                                        uint32_t a0, uint32_t a1, uint32_t a2, uint32_t a3,
                                        uint32_t b0, uint32_t b1) {
    asm volatile(
        "mma.sync.aligned.m16n8k16.row.col.f32.f16.f16.f32 "
        "{%0,%1,%2,%3},{%4,%5,%6,%7},{%8,%9},{%0,%1,%2,%3};"
        : "+f"(c0), "+f"(c1), "+f"(c2), "+f"(c3)
        : "r"(a0), "r"(a1), "r"(a2), "r"(a3), "r"(b0), "r"(b1));
}

// ---------------- fp16 tensor-core GEMM: K-chunked, barrier-free inner loop -
// CTA 128x128, 256 thr = 8 warps (2 x 4), warp tile 64x32, 2 CTAs/SM.
// NCHUNK sequential K=128 chunks share ONE 69.6KB smem buffer; per chunk:
// one cp.async group + 1 barrier, 8 fully-unrolled ldsm+mma steps (no sync),
// 1 barrier before the next chunk overwrites. Accumulators persist in regs.
// MODE 1 (conv1): K=128 (1 chunk), A=g_accX, B=g_W1h; C=half(relu(v+b1))->g_h1
// MODE 2 (conv2): K=256 (2 chunks), A=g_h1,  B=g_W2h; C=half(d_row*v)  ->g_g2h
extern __shared__ __half dsm_h[];

template <int MODE, int NCHUNK>
__global__ __launch_bounds__(256, 2)
void k_gemm_h(const float* __restrict__ bias, int M, int N) {
    const int K = NCHUNK * KC;

    __half* As = dsm_h;
    __half* Bs = dsm_h + 128 * STR;

    const __half* A  = (MODE == 1) ? g_accX : g_h1;
    const __half* Bw = (MODE == 1) ? g_W1h  : g_W2h;

    int tid  = threadIdx.x;
    int lane = tid & 31;
    int wid  = tid >> 5;
    int warp_m = wid & 1;   // 0..1 (64 rows)
    int warp_n = wid >> 1;  // 0..3 (32 cols)
    int bm = blockIdx.x * 128;
    int bn = blockIdx.y * 128;
    int lq = lane & 3;
    int lg = lane >> 2;

    float c[4][4][4];
#pragma unroll
    for (int mt = 0; mt < 4; mt++)
#pragma unroll
        for (int nt = 0; nt < 4; nt++)
#pragma unroll
            for (int r = 0; r < 4; r++) c[mt][nt][r] = 0.f;

    // per-thread load slots: 2048 chunks of 16B per panel-chunk, 8/thread
    const int CPR = KC / 8;                // 16 chunks per row
    uint32_t asb = (uint32_t)__cvta_generic_to_shared(As);
    uint32_t bsb = (uint32_t)__cvta_generic_to_shared(Bs);
    uint32_t lmOff = ((lane & 15) * STR + (lane >> 4) * 8) * 2;

#pragma unroll
    for (int ch = 0; ch < NCHUNK; ch++) {
        // ---- load chunk ch (one async group) ----
#pragma unroll
        for (int q = 0; q < 128 * CPR / 256; q++) {
            int idx = q * 256 + tid;
            int r   = idx / CPR;
            int ck  = idx % CPR;
            int gr  = bm + r;
            int ok  = (gr < M) ? 16 : 0;
            cpa16(&As[r * STR + ck * 8],
                  A + (size_t)min(gr, M - 1) * K + ch * KC + ck * 8, ok);
            cpa16(&Bs[r * STR + ck * 8],
                  Bw + (size_t)(bn + r) * K + ch * KC + ck * 8, 16);
        }
        cpa_commit();
        cpa_wait<0>();
        __syncthreads();

        // ---- barrier-free inner loop over this chunk's K ----
#pragma unroll
        for (int ks = 0; ks < KC / 16; ks++) {
            uint32_t kOff = ks * 16 * 2;
            uint32_t a[4][4];
#pragma unroll
            for (int mt = 0; mt < 4; mt++) {
                uint32_t addr = asb + (warp_m * 64 + mt * 16) * (STR * 2) + kOff + lmOff;
                ldsm4(a[mt][0], a[mt][1], a[mt][2], a[mt][3], addr);
            }
            uint32_t b[4][2];
#pragma unroll
            for (int ntp = 0; ntp < 2; ntp++) {
                uint32_t r0, r1, r2, r3;
                uint32_t addr = bsb + (warp_n * 32 + ntp * 16) * (STR * 2) + kOff + lmOff;
                ldsm4(r0, r1, r2, r3, addr);
                b[ntp * 2 + 0][0] = r0;
                b[ntp * 2 + 1][0] = r1;
                b[ntp * 2 + 0][1] = r2;
                b[ntp * 2 + 1][1] = r3;
            }
#pragma unroll
            for (int mt = 0; mt < 4; mt++)
#pragma unroll
                for (int nt = 0; nt < 4; nt++)
                    mma_f16(c[mt][nt][0], c[mt][nt][1], c[mt][nt][2], c[mt][nt][3],
                            a[mt][0], a[mt][1], a[mt][2], a[mt][3],
                            b[nt][0], b[nt][1]);
        }
        if (ch + 1 < NCHUNK) __syncthreads();   // WAR: buffer reuse
    }

    // ---- epilogue ----
#pragma unroll
    for (int mt = 0; mt < 4; mt++) {
        int row0 = bm + warp_m * 64 + mt * 16 + lg;
        int row1 = row0 + 8;
#pragma unroll
        for (int nt = 0; nt < 4; nt++) {
            int col = bn + warp_n * 32 + nt * 8 + lq * 2;
            if (MODE == 1) {
                float2 bb = *(const float2*)(bias + col);
                if (row0 < M) {
                    __half2 v = __floats2half2_rn(fmaxf(c[mt][nt][0] + bb.x, 0.f),
                                                  fmaxf(c[mt][nt][1] + bb.y, 0.f));
                    *(unsigned*)(g_h1 + (size_t)row0 * N + col) =
                        *reinterpret_cast<const unsigned*>(&v);
                }
                if (row1 < M) {
                    __half2 v = __floats2half2_rn(fmaxf(c[mt][nt][2] + bb.x, 0.f),
                                                  fmaxf(c[mt][nt][3] + bb.y, 0.f));
                    *(unsigned*)(g_h1 + (size_t)row1 * N + col) =
                        *reinterpret_cast<const unsigned*>(&v);
                }
            } else {
                if (row0 < M) {
                    float s0 = disq(g_cnt[row0]);
                    __half2 v = __floats2half2_rn(c[mt][nt][0] * s0, c[mt][nt][1] * s0);
                    *(unsigned*)(g_g2h + (size_t)row0 * N + col) =
                        *reinterpret_cast<const unsigned*>(&v);
                }
                if (row1 < M) {
                    float s1 = disq(g_cnt[row1]);
                    __half2 v = __floats2half2_rn(c[mt][nt][2] * s1, c[mt][nt][3] * s1);
                    *(unsigned*)(g_g2h + (size_t)row1 * N + col) =
                        *reinterpret_cast<const unsigned*>(&v);
                }
            }
        }
    }
}

// ---------------- fused layer-2 gather + FC head (clears g_cnt) -------------
__global__ void k_gather2fc(const float* __restrict__ Wfc, const float* __restrict__ bfc,
                            const float* __restrict__ b2, float* __restrict__ out, int n) {
    int gtid = blockIdx.x * blockDim.x + threadIdx.x;
    int w = gtid >> 5;
    int lane = threadIdx.x & 31;
    if (w >= n) return;

    int cnt = g_cnt[w];
    int len = min(cnt, CAP);
    float s = disq(cnt);

    uint2 gv = ((const uint2*)g_g2h)[(size_t)w * 32 + lane];
    float2 acc01 = __half22float2(*reinterpret_cast<__half2*>(&gv.x));
    float2 acc23 = __half22float2(*reinterpret_cast<__half2*>(&gv.y));

    gather_row_h(g_g2h, w * CAP, len, lane, acc01, acc23);

    if (lane == 0) g_cnt[w] = 0;   // self-clear for next replay

    float4 bb = ((const float4*)b2)[lane];
    float h[4];
    h[0] = fmaxf(acc01.x * s + bb.x, 0.f);
    h[1] = fmaxf(acc01.y * s + bb.y, 0.f);
    h[2] = fmaxf(acc23.x * s + bb.z, 0.f);
    h[3] = fmaxf(acc23.y * s + bb.w, 0.f);

    int c0 = lane * 4;
    float a6[DOUT];
#pragma unroll
    for (int o = 0; o < DOUT; o++) a6[o] = 0.f;
#pragma unroll
    for (int j = 0; j < 4; j++)
#pragma unroll
        for (int o = 0; o < DOUT; o++)
            a6[o] += h[j] * __ldg(&Wfc[(c0 + j) * DOUT + o]);
#pragma unroll
    for (int o = 0; o < DOUT; o++)
        for (int off = 16; off; off >>= 1)
            a6[o] += __shfl_xor_sync(0xffffffffu, a6[o], off);
    if (lane == 0) {
#pragma unroll
        for (int o = 0; o < DOUT; o++) out[(size_t)w * DOUT + o] = a6[o] + bfc[o];
    }
}

// ---------------- launch ----------------------------------------------------
extern "C" void kernel_launch(void* const* d_in, const int* in_sizes, int n_in,
                              void* d_out, int out_size) {
    const float* x   = (const float*)d_in[0];
    const float* W1  = (const float*)d_in[1];
    const float* b1  = (const float*)d_in[2];
    const float* W2  = (const float*)d_in[3];
    const float* b2  = (const float*)d_in[4];
    const float* Wfc = (const float*)d_in[5];
    const float* bfc = (const float*)d_in[6];
    const int*   ei  = (const int*)d_in[7];

    int n = in_sizes[0] / DIN;
    int E = in_sizes[7] / 2;
    const int* src = ei;
    const int* dst = ei + E;
    float* out = (float*)d_out;

    // dynamic smem opt-in (host-side attribute set; not a stream op)
    const int SMB = 2 * 128 * STR * 2;   // 69,632 B -> 2 CTAs/SM
    static bool attr_done = false;
    if (!attr_done) {
        cudaFuncSetAttribute(k_gemm_h<1, 1>, cudaFuncAttributeMaxDynamicSharedMemorySize, SMB);
        cudaFuncSetAttribute(k_gemm_h<2, 2>, cudaFuncAttributeMaxDynamicSharedMemorySize, SMB);
        attr_done = true;
    }

    // adjacency + degrees + weight convert (merged)
    int fillBlocks = (E + 255) / 256;
    int roundBlocks = (DIN * H1 + 255) / 256;
    k_fillround<<<fillBlocks + roundBlocks, 256>>>(src, dst, E, fillBlocks, W1, W2);
    k_xhalf<<<(n * 32 + 255) / 256, 256>>>(x, n);

    // layer 1
    k_gather1<<<(n * 32 + 255) / 256, 256>>>(n);
    {
        dim3 grid((n + 127) / 128, H1 / 128);
        k_gemm_h<1, 1><<<grid, 256, SMB>>>(b1, n, H1);
    }

    // layer 2
    {
        dim3 grid((n + 127) / 128, H2 / 128);
        k_gemm_h<2, 2><<<grid, 256, SMB>>>(nullptr, n, H2);
    }
    k_gather2fc<<<(n * 32 + 255) / 256, 256>>>(Wfc, bfc, b2, out, n);
}